// round 8
// baseline (speedup 1.0000x reference)
#include <cuda_runtime.h>
#include <cuda_bf16.h>
#include <cstdint>

// ---------------------------------------------------------------------------
// 2-layer GRU (H=32, INPUT=4, B=4096, S=512) + FC(32->32) + FC(32->1)
//
// Three kernels:
//  1) gru_layer1: recurrent layer 1, x -> h1            (warp/row, 3 w/SMSP)
//  2) xg_gemm:    xg2 = h1 @ W_ih1^T + biases (no recurrence, full ILP)
//  3) gru_layer2: recurrent h-side only (48 FFMA2/step) + FC epilogue
// ---------------------------------------------------------------------------

#define B_ROWS 4096
#define SEQ    512
#define HID    32
#define RING   8

typedef unsigned long long ull;

__device__ float g_h1[(size_t)B_ROWS * SEQ * HID];   // 268 MB
__device__ float g_xg[(size_t)B_ROWS * SEQ * 96];    // 805 MB

__device__ __forceinline__ ull ffma2(ull a, ull b, ull c) {
    ull d;
    asm("fma.rn.f32x2 %0, %1, %2, %3;" : "=l"(d) : "l"(a), "l"(b), "l"(c));
    return d;
}
__device__ __forceinline__ float hsum2(ull v) {
    float2 r;
    asm("mov.b64 {%0, %1}, %2;" : "=f"(r.x), "=f"(r.y) : "l"(v));
    return r.x + r.y;
}
__device__ __forceinline__ float tanh_ap(float x) {
    float y;
    asm("tanh.approx.f32 %0, %1;" : "=f"(y) : "f"(x));
    return y;
}
__device__ __forceinline__ float sig_ap(float x) {
    return fmaf(0.5f, tanh_ap(0.5f * x), 0.5f);
}
__device__ __forceinline__ void cp_async4(uint32_t smem_addr, const float* gptr) {
    asm volatile("cp.async.ca.shared.global [%0], [%1], 4;"
                 :: "r"(smem_addr), "l"(gptr));
}
__device__ __forceinline__ void cp_commit() {
    asm volatile("cp.async.commit_group;");
}
__device__ __forceinline__ void cp_wait_ring() {
    asm volatile("cp.async.wait_group %0;" :: "n"(RING - 1));
}

// ---------------------------------------------------------------------------
// Pass 1: GRU layer 1.  x:[B,S,4] -> h1:[B,S,32]
// ---------------------------------------------------------------------------
__global__ __launch_bounds__(128, 3)
void gru_layer1_kernel(const float* __restrict__ x,
                       const float* __restrict__ Wih,   // [96,4]
                       const float* __restrict__ Whh,   // [96,32]
                       const float* __restrict__ bih,   // [96]
                       const float* __restrict__ bhh)   // [96]
{
    __shared__ __align__(16) float hbuf[4][2][HID];
    __shared__ __align__(16) float xring[4][RING][4];

    const int warp = (blockIdx.x * blockDim.x + threadIdx.x) >> 5;
    const int wl   = threadIdx.x >> 5;
    const int lane = threadIdx.x & 31;
    if (warp >= B_ROWS) return;

    ull whr[16], whz[16], whn[16];
    {
        const ull* pr = reinterpret_cast<const ull*>(Whh + (lane)      * HID);
        const ull* pz = reinterpret_cast<const ull*>(Whh + (32 + lane) * HID);
        const ull* pn = reinterpret_cast<const ull*>(Whh + (64 + lane) * HID);
#pragma unroll
        for (int k = 0; k < 16; k++) { whr[k] = pr[k]; whz[k] = pz[k]; whn[k] = pn[k]; }
    }
    const float4 wir = reinterpret_cast<const float4*>(Wih)[lane];
    const float4 wiz = reinterpret_cast<const float4*>(Wih)[32 + lane];
    const float4 win = reinterpret_cast<const float4*>(Wih)[64 + lane];

    const float br  = bih[lane]      + bhh[lane];
    const float bz  = bih[32 + lane] + bhh[32 + lane];
    const float bin = bih[64 + lane];
    const float bhn = bhh[64 + lane];

    const float* xsrc = x + (size_t)warp * SEQ * 4;
    float* op = g_h1 + (size_t)warp * SEQ * HID + lane;

    const uint32_t ring_base =
        (uint32_t)__cvta_generic_to_shared(&xring[wl][0][0]);

#pragma unroll
    for (int d = 0; d < RING; d++) {
        if (lane < 4) cp_async4(ring_base + d * 16 + lane * 4, xsrc + d * 4 + lane);
        cp_commit();
    }

    float h = 0.0f;
#pragma unroll 1
    for (int s = 0; s < SEQ; s++) {
        hbuf[wl][s & 1][lane] = h;
        cp_wait_ring();
        __syncwarp();

        const float4 xv =
            *reinterpret_cast<const float4*>(&xring[wl][s & (RING - 1)][0]);
        const ulonglong2* hp =
            reinterpret_cast<const ulonglong2*>(&hbuf[wl][s & 1][0]);

        if (lane < 4 && s + RING < SEQ)
            cp_async4(ring_base + ((s + RING) & (RING - 1)) * 16 + lane * 4,
                      xsrc + (s + RING) * 4 + lane);
        cp_commit();

        float ar = br, az = bz, xn = bin;
        ar = fmaf(wir.x, xv.x, ar); ar = fmaf(wir.y, xv.y, ar);
        ar = fmaf(wir.z, xv.z, ar); ar = fmaf(wir.w, xv.w, ar);
        az = fmaf(wiz.x, xv.x, az); az = fmaf(wiz.y, xv.y, az);
        az = fmaf(wiz.z, xv.z, az); az = fmaf(wiz.w, xv.w, az);
        xn = fmaf(win.x, xv.x, xn); xn = fmaf(win.y, xv.y, xn);
        xn = fmaf(win.z, xv.z, xn); xn = fmaf(win.w, xv.w, xn);

        ull accr = 0ull, accz = 0ull, accn = 0ull;
#pragma unroll
        for (int k = 0; k < 8; k++) {
            const ulonglong2 hv = hp[k];
            accr = ffma2(whr[2 * k],     hv.x, accr);
            accz = ffma2(whz[2 * k],     hv.x, accz);
            accn = ffma2(whn[2 * k],     hv.x, accn);
            accr = ffma2(whr[2 * k + 1], hv.y, accr);
            accz = ffma2(whz[2 * k + 1], hv.y, accz);
            accn = ffma2(whn[2 * k + 1], hv.y, accn);
        }
        ar += hsum2(accr);
        az += hsum2(accz);
        const float hn = bhn + hsum2(accn);

        const float r = sig_ap(ar);
        const float z = sig_ap(az);
        const float n = tanh_ap(fmaf(r, hn, xn));
        h = fmaf(z, h - n, n);

        op[(size_t)s * HID] = h;
    }
}

// ---------------------------------------------------------------------------
// GEMM: xg2[r,96] = h1[r,:] @ W_ih1^T + b_ih1 (+ b_hh1 folded for r,z gates)
// Warp handles 32 consecutive rows; lane owns gate rows {lane,32+lane,64+lane}.
// ---------------------------------------------------------------------------
__global__ __launch_bounds__(128, 4)
void xg_gemm_kernel(const float* __restrict__ Wih,   // [96,32]
                    const float* __restrict__ bih,   // [96]
                    const float* __restrict__ bhh)   // [96]
{
    const int gwarp = (blockIdx.x * blockDim.x + threadIdx.x) >> 5;
    const int lane  = threadIdx.x & 31;

    ull wxr[16], wxz[16], wxn[16];
    {
        const ull* p0 = reinterpret_cast<const ull*>(Wih + (lane)      * HID);
        const ull* p1 = reinterpret_cast<const ull*>(Wih + (32 + lane) * HID);
        const ull* p2 = reinterpret_cast<const ull*>(Wih + (64 + lane) * HID);
#pragma unroll
        for (int k = 0; k < 16; k++) { wxr[k] = p0[k]; wxz[k] = p1[k]; wxn[k] = p2[k]; }
    }
    const float bxr = bih[lane]      + bhh[lane];        // fold r-gate bhh
    const float bxz = bih[32 + lane] + bhh[32 + lane];   // fold z-gate bhh
    const float bxn = bih[64 + lane];                    // n-gate bhh stays out

    const float* rowbase = g_h1 + (size_t)gwarp * 32 * HID;
    float*       outbase = g_xg + (size_t)gwarp * 32 * 96;

#pragma unroll 2
    for (int i = 0; i < 32; i++) {
        const ulonglong2* hp =
            reinterpret_cast<const ulonglong2*>(rowbase + i * HID);
        ull a0 = 0ull, a1 = 0ull, a2 = 0ull;
#pragma unroll
        for (int k = 0; k < 8; k++) {
            const ulonglong2 hv = __ldg(hp + k);   // uniform LDG.128 broadcast
            a0 = ffma2(wxr[2 * k],     hv.x, a0);
            a1 = ffma2(wxz[2 * k],     hv.x, a1);
            a2 = ffma2(wxn[2 * k],     hv.x, a2);
            a0 = ffma2(wxr[2 * k + 1], hv.y, a0);
            a1 = ffma2(wxz[2 * k + 1], hv.y, a1);
            a2 = ffma2(wxn[2 * k + 1], hv.y, a2);
        }
        float* o = outbase + i * 96;
        o[lane]      = bxr + hsum2(a0);
        o[32 + lane] = bxz + hsum2(a1);
        o[64 + lane] = bxn + hsum2(a2);
    }
}

// ---------------------------------------------------------------------------
// Pass 2: GRU layer 2 recurrence (h-side only) + FC(32->32) + FC(32->1)
// ---------------------------------------------------------------------------
__global__ __launch_bounds__(128, 3)
void gru_layer2_fc_kernel(const float* __restrict__ Whh,   // [96,32]
                          const float* __restrict__ bhh,   // [96]
                          const float* __restrict__ Wfc2,  // [32,32]
                          const float* __restrict__ bfc2,  // [32]
                          const float* __restrict__ Wfc,   // [1,32]
                          const float* __restrict__ bfc,   // [1]
                          float* __restrict__ out)
{
    __shared__ __align__(16) float hbuf[4][2][HID];
    __shared__ __align__(16) float xring[4][RING][96];   // 384B rows

    const int warp = (blockIdx.x * blockDim.x + threadIdx.x) >> 5;
    const int wl   = threadIdx.x >> 5;
    const int lane = threadIdx.x & 31;
    if (warp >= B_ROWS) return;

    ull whr[16], whz[16], whn[16];
    {
        const ull* p3 = reinterpret_cast<const ull*>(Whh + (lane)      * HID);
        const ull* p4 = reinterpret_cast<const ull*>(Whh + (32 + lane) * HID);
        const ull* p5 = reinterpret_cast<const ull*>(Whh + (64 + lane) * HID);
#pragma unroll
        for (int k = 0; k < 16; k++) { whr[k] = p3[k]; whz[k] = p4[k]; whn[k] = p5[k]; }
    }
    const float bhn = bhh[64 + lane];

    const float* xsrc = g_xg + (size_t)warp * SEQ * 96;

    const uint32_t ring_base =
        (uint32_t)__cvta_generic_to_shared(&xring[wl][0][0]);

    // Prologue: stage rows 0..RING-1 (each lane carries 12B of the 384B row)
#pragma unroll
    for (int d = 0; d < RING; d++) {
        cp_async4(ring_base + d * 384 + lane * 4,       xsrc + d * 96 + lane);
        cp_async4(ring_base + d * 384 + 128 + lane * 4, xsrc + d * 96 + 32 + lane);
        cp_async4(ring_base + d * 384 + 256 + lane * 4, xsrc + d * 96 + 64 + lane);
        cp_commit();
    }

    float h = 0.0f;
#pragma unroll 1
    for (int s = 0; s < SEQ; s++) {
        hbuf[wl][s & 1][lane] = h;
        cp_wait_ring();
        __syncwarp();

        const float* xr_row = &xring[wl][s & (RING - 1)][0];
        const float xr = xr_row[lane];         // bih+bhh already folded
        const float xz = xr_row[32 + lane];
        const float xn = xr_row[64 + lane];    // bih folded
        const ulonglong2* hp =
            reinterpret_cast<const ulonglong2*>(&hbuf[wl][s & 1][0]);

        if (s + RING < SEQ) {
            const float* g = xsrc + (s + RING) * 96;
            const uint32_t rb = ring_base + ((s + RING) & (RING - 1)) * 384;
            cp_async4(rb + lane * 4,       g + lane);
            cp_async4(rb + 128 + lane * 4, g + 32 + lane);
            cp_async4(rb + 256 + lane * 4, g + 64 + lane);
        }
        cp_commit();

        ull a0 = 0ull, a1 = 0ull, a2 = 0ull;
#pragma unroll
        for (int k = 0; k < 8; k++) {
            const ulonglong2 hv = hp[k];
            a0 = ffma2(whr[2 * k],     hv.x, a0);
            a1 = ffma2(whz[2 * k],     hv.x, a1);
            a2 = ffma2(whn[2 * k],     hv.x, a2);
            a0 = ffma2(whr[2 * k + 1], hv.y, a0);
            a1 = ffma2(whz[2 * k + 1], hv.y, a1);
            a2 = ffma2(whn[2 * k + 1], hv.y, a2);
        }
        const float ar = xr + hsum2(a0);
        const float az = xz + hsum2(a1);
        const float hn = bhn + hsum2(a2);

        const float r = sig_ap(ar);
        const float z = sig_ap(az);
        const float n = tanh_ap(fmaf(r, hn, xn));
        h = fmaf(z, h - n, n);
    }

    // FC2 + FC epilogue
    {
        hbuf[wl][0][lane] = h;
        __syncwarp();
        const ulonglong2* hp = reinterpret_cast<const ulonglong2*>(&hbuf[wl][0][0]);
        const ull* wf = reinterpret_cast<const ull*>(Wfc2 + lane * HID);
        ull acc = 0ull;
#pragma unroll
        for (int k = 0; k < 8; k++) {
            const ulonglong2 hv = hp[k];
            acc = ffma2(wf[2 * k],     hv.x, acc);
            acc = ffma2(wf[2 * k + 1], hv.y, acc);
        }
        const float o = __ldg(bfc2 + lane) + hsum2(acc);

        float p = __ldg(Wfc + lane) * o;
#pragma unroll
        for (int off = 16; off > 0; off >>= 1)
            p += __shfl_xor_sync(0xffffffffu, p, off);
        if (lane == 0) out[warp] = p + __ldg(bfc);
    }
}

// ---------------------------------------------------------------------------
// Launch
// ---------------------------------------------------------------------------
extern "C" void kernel_launch(void* const* d_in, const int* in_sizes, int n_in,
                              void* d_out, int out_size)
{
    const float* x     = (const float*)d_in[0];
    const float* Wih0  = (const float*)d_in[1];
    const float* Whh0  = (const float*)d_in[2];
    const float* bih0  = (const float*)d_in[3];
    const float* bhh0  = (const float*)d_in[4];
    const float* Wih1  = (const float*)d_in[5];
    const float* Whh1  = (const float*)d_in[6];
    const float* bih1  = (const float*)d_in[7];
    const float* bhh1  = (const float*)d_in[8];
    const float* Wfc2  = (const float*)d_in[9];
    const float* bfc2  = (const float*)d_in[10];
    const float* Wfc   = (const float*)d_in[11];
    const float* bfc   = (const float*)d_in[12];
    float* out = (float*)d_out;

    const int threads = 128;
    const int blocks  = B_ROWS / (threads / 32);          // 1024

    // total rows = B*SEQ = 2M; 32 rows/warp, 4 warps/CTA -> 16384 CTAs
    const int gemm_blocks = (B_ROWS * SEQ) / (32 * 4);

    gru_layer1_kernel<<<blocks, threads>>>(x, Wih0, Whh0, bih0, bhh0);
    xg_gemm_kernel<<<gemm_blocks, threads>>>(Wih1, bih1, bhh1);
    gru_layer2_fc_kernel<<<blocks, threads>>>(Whh1, bhh1,
                                              Wfc2, bfc2, Wfc, bfc, out);
}

// round 9
// speedup vs baseline: 1.3993x; 1.3993x over previous
#include <cuda_runtime.h>
#include <cuda_bf16.h>
#include <cstdint>

// ---------------------------------------------------------------------------
// 2-layer GRU (H=32, INPUT=4, B=4096, S=512) + FC(32->32) + FC(32->1)
//
// Two kernels (R6 structure), occupancy raised by sharing per-CTA-identical
// weight blocks through shared memory instead of registers:
//  pass 1: n-gate recurrent weights in smem -> 4 warps/SMSP
//  pass 2: x-side (W_ih1) weights in smem   -> 3 warps/SMSP
// ---------------------------------------------------------------------------

#define B_ROWS 4096
#define SEQ    512
#define HID    32
#define RING   8

typedef unsigned long long ull;

__device__ float g_h1[(size_t)B_ROWS * SEQ * HID];   // 268 MB scratch

__device__ __forceinline__ ull ffma2(ull a, ull b, ull c) {
    ull d;
    asm("fma.rn.f32x2 %0, %1, %2, %3;" : "=l"(d) : "l"(a), "l"(b), "l"(c));
    return d;
}
__device__ __forceinline__ float hsum2(ull v) {
    float2 r;
    asm("mov.b64 {%0, %1}, %2;" : "=f"(r.x), "=f"(r.y) : "l"(v));
    return r.x + r.y;
}
__device__ __forceinline__ float tanh_ap(float x) {
    float y;
    asm("tanh.approx.f32 %0, %1;" : "=f"(y) : "f"(x));
    return y;
}
__device__ __forceinline__ float sig_ap(float x) {
    return fmaf(0.5f, tanh_ap(0.5f * x), 0.5f);
}
__device__ __forceinline__ void cp_async4(uint32_t smem_addr, const float* gptr) {
    asm volatile("cp.async.ca.shared.global [%0], [%1], 4;"
                 :: "r"(smem_addr), "l"(gptr));
}
__device__ __forceinline__ void cp_commit() {
    asm volatile("cp.async.commit_group;");
}
__device__ __forceinline__ void cp_wait_ring() {
    asm volatile("cp.async.wait_group %0;" :: "n"(RING - 1));
}

// ---------------------------------------------------------------------------
// Pass 1: GRU layer 1.  x:[B,S,4] -> h1:[B,S,32]
//   r,z recurrent weights in registers; n-gate recurrent weights in smem.
// ---------------------------------------------------------------------------
__global__ __launch_bounds__(128, 4)
void gru_layer1_kernel(const float* __restrict__ x,
                       const float* __restrict__ Wih,   // [96,4]
                       const float* __restrict__ Whh,   // [96,32]
                       const float* __restrict__ bih,   // [96]
                       const float* __restrict__ bhh)   // [96]
{
    __shared__ __align__(16) float hbuf[4][2][HID];
    __shared__ __align__(16) float xring[4][RING][4];
    __shared__ __align__(16) ulonglong2 wn_s[8][32];   // n-gate Whh, 4KB

    const int warp = (blockIdx.x * blockDim.x + threadIdx.x) >> 5;
    const int wl   = threadIdx.x >> 5;
    const int lane = threadIdx.x & 31;

    // Cooperative one-time load of n-gate recurrent weights.
    for (int idx = threadIdx.x; idx < 8 * 32; idx += blockDim.x) {
        const int k  = idx >> 5;
        const int ln = idx & 31;
        wn_s[k][ln] =
            *reinterpret_cast<const ulonglong2*>(Whh + (64 + ln) * HID + 4 * k);
    }
    __syncthreads();
    if (warp >= B_ROWS) return;

    ull whr[16], whz[16];
    {
        const ull* pr = reinterpret_cast<const ull*>(Whh + (lane)      * HID);
        const ull* pz = reinterpret_cast<const ull*>(Whh + (32 + lane) * HID);
#pragma unroll
        for (int k = 0; k < 16; k++) { whr[k] = pr[k]; whz[k] = pz[k]; }
    }
    const float4 wir = reinterpret_cast<const float4*>(Wih)[lane];
    const float4 wiz = reinterpret_cast<const float4*>(Wih)[32 + lane];
    const float4 win = reinterpret_cast<const float4*>(Wih)[64 + lane];

    const float br  = bih[lane]      + bhh[lane];
    const float bz  = bih[32 + lane] + bhh[32 + lane];
    const float bin = bih[64 + lane];
    const float bhn = bhh[64 + lane];

    const float* xsrc = x + (size_t)warp * SEQ * 4;
    float* op = g_h1 + (size_t)warp * SEQ * HID + lane;

    const uint32_t ring_base =
        (uint32_t)__cvta_generic_to_shared(&xring[wl][0][0]);

#pragma unroll
    for (int d = 0; d < RING; d++) {
        if (lane < 4) cp_async4(ring_base + d * 16 + lane * 4, xsrc + d * 4 + lane);
        cp_commit();
    }

    float h = 0.0f;
#pragma unroll 1
    for (int s = 0; s < SEQ; s++) {
        hbuf[wl][s & 1][lane] = h;
        cp_wait_ring();
        __syncwarp();

        const float4 xv =
            *reinterpret_cast<const float4*>(&xring[wl][s & (RING - 1)][0]);
        const ulonglong2* hp =
            reinterpret_cast<const ulonglong2*>(&hbuf[wl][s & 1][0]);

        if (lane < 4 && s + RING < SEQ)
            cp_async4(ring_base + ((s + RING) & (RING - 1)) * 16 + lane * 4,
                      xsrc + (s + RING) * 4 + lane);
        cp_commit();

        float ar = br, az = bz, xn = bin;
        ar = fmaf(wir.x, xv.x, ar); ar = fmaf(wir.y, xv.y, ar);
        ar = fmaf(wir.z, xv.z, ar); ar = fmaf(wir.w, xv.w, ar);
        az = fmaf(wiz.x, xv.x, az); az = fmaf(wiz.y, xv.y, az);
        az = fmaf(wiz.z, xv.z, az); az = fmaf(wiz.w, xv.w, az);
        xn = fmaf(win.x, xv.x, xn); xn = fmaf(win.y, xv.y, xn);
        xn = fmaf(win.z, xv.z, xn); xn = fmaf(win.w, xv.w, xn);

        ull accr = 0ull, accz = 0ull, accn = 0ull;
#pragma unroll
        for (int k = 0; k < 8; k++) {
            const ulonglong2 hv = hp[k];
            const ulonglong2 wn = wn_s[k][lane];
            accr = ffma2(whr[2 * k],     hv.x, accr);
            accz = ffma2(whz[2 * k],     hv.x, accz);
            accn = ffma2(wn.x,           hv.x, accn);
            accr = ffma2(whr[2 * k + 1], hv.y, accr);
            accz = ffma2(whz[2 * k + 1], hv.y, accz);
            accn = ffma2(wn.y,           hv.y, accn);
        }
        ar += hsum2(accr);
        az += hsum2(accz);
        const float hn = bhn + hsum2(accn);

        const float r = sig_ap(ar);
        const float z = sig_ap(az);
        const float n = tanh_ap(fmaf(r, hn, xn));
        h = fmaf(z, h - n, n);

        op[(size_t)s * HID] = h;
    }
}

// ---------------------------------------------------------------------------
// Pass 2: GRU layer 2 + FC(32->32) + FC(32->1).  h1:[B,S,32] -> out:[B]
//   Recurrent (Whh) weights in registers; input-side (Wih) weights in smem.
// ---------------------------------------------------------------------------
__global__ __launch_bounds__(128, 3)
void gru_layer2_fc_kernel(const float* __restrict__ Wih,   // [96,32]
                          const float* __restrict__ Whh,   // [96,32]
                          const float* __restrict__ bih,   // [96]
                          const float* __restrict__ bhh,   // [96]
                          const float* __restrict__ Wfc2,  // [32,32]
                          const float* __restrict__ bfc2,  // [32]
                          const float* __restrict__ Wfc,   // [1,32]
                          const float* __restrict__ bfc,   // [1]
                          float* __restrict__ out)
{
    __shared__ __align__(16) float hbuf[4][2][HID];
    __shared__ __align__(16) float xring[4][RING][HID];    // h1 rows, 128B
    __shared__ __align__(16) ulonglong2 xw_s[3][8][32];    // W_ih1, 12KB

    const int warp = (blockIdx.x * blockDim.x + threadIdx.x) >> 5;
    const int wl   = threadIdx.x >> 5;
    const int lane = threadIdx.x & 31;

    // Cooperative one-time load of x-side weights (gate-major).
    for (int idx = threadIdx.x; idx < 3 * 8 * 32; idx += blockDim.x) {
        const int g   = idx >> 8;
        const int rem = idx & 255;
        const int k   = rem >> 5;
        const int ln  = rem & 31;
        xw_s[g][k][ln] =
            *reinterpret_cast<const ulonglong2*>(Wih + (g * 32 + ln) * HID + 4 * k);
    }
    __syncthreads();
    if (warp >= B_ROWS) return;

    ull whr[16], whz[16], whn[16];
    {
        const ull* p3 = reinterpret_cast<const ull*>(Whh + (lane)      * HID);
        const ull* p4 = reinterpret_cast<const ull*>(Whh + (32 + lane) * HID);
        const ull* p5 = reinterpret_cast<const ull*>(Whh + (64 + lane) * HID);
#pragma unroll
        for (int k = 0; k < 16; k++) { whr[k] = p3[k]; whz[k] = p4[k]; whn[k] = p5[k]; }
    }
    const float br  = bih[lane]      + bhh[lane];
    const float bz  = bih[32 + lane] + bhh[32 + lane];
    const float bin = bih[64 + lane];
    const float bhn = bhh[64 + lane];

    const float* xsrc = g_h1 + (size_t)warp * SEQ * HID;

    const uint32_t ring_base =
        (uint32_t)__cvta_generic_to_shared(&xring[wl][0][0]);

#pragma unroll
    for (int d = 0; d < RING; d++) {
        cp_async4(ring_base + d * 128 + lane * 4, xsrc + d * HID + lane);
        cp_commit();
    }

    float h = 0.0f;
#pragma unroll 1
    for (int s = 0; s < SEQ; s++) {
        hbuf[wl][s & 1][lane] = h;
        cp_wait_ring();
        __syncwarp();

        const ulonglong2* xp =
            reinterpret_cast<const ulonglong2*>(&xring[wl][s & (RING - 1)][0]);
        const ulonglong2* hp =
            reinterpret_cast<const ulonglong2*>(&hbuf[wl][s & 1][0]);

        if (s + RING < SEQ)
            cp_async4(ring_base + ((s + RING) & (RING - 1)) * 128 + lane * 4,
                      xsrc + (s + RING) * HID + lane);
        cp_commit();

        ull a_r = 0ull, a_z = 0ull, a_xn = 0ull, a_hn = 0ull;
#pragma unroll
        for (int k = 0; k < 8; k++) {
            const ulonglong2 xv = xp[k];
            const ulonglong2 hv = hp[k];
            const ulonglong2 w0 = xw_s[0][k][lane];
            const ulonglong2 w1 = xw_s[1][k][lane];
            const ulonglong2 w2 = xw_s[2][k][lane];
            a_r  = ffma2(w0.x,           xv.x, a_r);
            a_z  = ffma2(w1.x,           xv.x, a_z);
            a_xn = ffma2(w2.x,           xv.x, a_xn);
            a_r  = ffma2(whr[2 * k],     hv.x, a_r);
            a_z  = ffma2(whz[2 * k],     hv.x, a_z);
            a_hn = ffma2(whn[2 * k],     hv.x, a_hn);
            a_r  = ffma2(w0.y,           xv.y, a_r);
            a_z  = ffma2(w1.y,           xv.y, a_z);
            a_xn = ffma2(w2.y,           xv.y, a_xn);
            a_r  = ffma2(whr[2 * k + 1], hv.y, a_r);
            a_z  = ffma2(whz[2 * k + 1], hv.y, a_z);
            a_hn = ffma2(whn[2 * k + 1], hv.y, a_hn);
        }
        const float ar = br  + hsum2(a_r);
        const float az = bz  + hsum2(a_z);
        const float xn = bin + hsum2(a_xn);
        const float hn = bhn + hsum2(a_hn);

        const float r = sig_ap(ar);
        const float z = sig_ap(az);
        const float n = tanh_ap(fmaf(r, hn, xn));
        h = fmaf(z, h - n, n);
    }

    // FC2 + FC epilogue
    {
        hbuf[wl][0][lane] = h;
        __syncwarp();
        const ulonglong2* hp = reinterpret_cast<const ulonglong2*>(&hbuf[wl][0][0]);
        const ull* wf = reinterpret_cast<const ull*>(Wfc2 + lane * HID);
        ull acc = 0ull;
#pragma unroll
        for (int k = 0; k < 8; k++) {
            const ulonglong2 hv = hp[k];
            acc = ffma2(wf[2 * k],     hv.x, acc);
            acc = ffma2(wf[2 * k + 1], hv.y, acc);
        }
        const float o = __ldg(bfc2 + lane) + hsum2(acc);

        float p = __ldg(Wfc + lane) * o;
#pragma unroll
        for (int off = 16; off > 0; off >>= 1)
            p += __shfl_xor_sync(0xffffffffu, p, off);
        if (lane == 0) out[warp] = p + __ldg(bfc);
    }
}

// ---------------------------------------------------------------------------
// Launch
// ---------------------------------------------------------------------------
extern "C" void kernel_launch(void* const* d_in, const int* in_sizes, int n_in,
                              void* d_out, int out_size)
{
    const float* x     = (const float*)d_in[0];
    const float* Wih0  = (const float*)d_in[1];
    const float* Whh0  = (const float*)d_in[2];
    const float* bih0  = (const float*)d_in[3];
    const float* bhh0  = (const float*)d_in[4];
    const float* Wih1  = (const float*)d_in[5];
    const float* Whh1  = (const float*)d_in[6];
    const float* bih1  = (const float*)d_in[7];
    const float* bhh1  = (const float*)d_in[8];
    const float* Wfc2  = (const float*)d_in[9];
    const float* bfc2  = (const float*)d_in[10];
    const float* Wfc   = (const float*)d_in[11];
    const float* bfc   = (const float*)d_in[12];
    float* out = (float*)d_out;

    const int threads = 128;
    const int blocks  = B_ROWS / (threads / 32);   // 1024

    gru_layer1_kernel<<<blocks, threads>>>(x, Wih0, Whh0, bih0, bhh0);
    gru_layer2_fc_kernel<<<blocks, threads>>>(Wih1, Whh1, bih1, bhh1,
                                              Wfc2, bfc2, Wfc, bfc, out);
}